// round 1
// baseline (speedup 1.0000x reference)
#include <cuda_runtime.h>
#include <cstdint>

#define MLEN 16
#define DDIM 128
#define LNUM 26
#define KP   13      // LNUM/2 packed pairs
#define BPB  128     // batch elements per block
#define NTHR 128
#define XSTR 132     // padded floats per X row in smem (conflict-free LDS.128)
#define ETSTR 14     // float2 per expT row (pad 13 -> 14 for 16B alignment)

__device__ float g_partials[512];

static __device__ __forceinline__ unsigned long long pack2(float lo, float hi){
    unsigned long long r;
    asm("mov.b64 %0, {%1,%2};" : "=l"(r) : "f"(lo), "f"(hi));
    return r;
}
static __device__ __forceinline__ void unpack2(unsigned long long v, float& lo, float& hi){
    asm("mov.b64 {%0,%1}, %2;" : "=f"(lo), "=f"(hi) : "l"(v));
}
// packed dual-FMA: d.lo += a.lo*b.lo; d.hi += a.hi*b.hi  (2x FFMA throughput)
static __device__ __forceinline__ void ffma2(unsigned long long& d, unsigned long long a, unsigned long long b){
    asm("fma.rn.f32x2 %0, %1, %2, %0;" : "+l"(d) : "l"(a), "l"(b));
}
static __device__ __forceinline__ void cp16(uint32_t dst, const void* src){
    asm volatile("cp.async.cg.shared.global [%0], [%1], 16;" :: "r"(dst), "l"(src));
}

__global__ __launch_bounds__(NTHR, 1)
void crf_main(const float* __restrict__ X, const void* __restrict__ Yv,
              const float* __restrict__ W, const float* __restrict__ T)
{
    extern __shared__ float sm[];
    float* Xs0 = sm;                       // BPB*XSTR
    float* Xs1 = Xs0 + BPB * XSTR;         // BPB*XSTR
    float* Wil = Xs1 + BPB * XSTR;         // 64*KP*4 floats (interleaved k-pair layout)
    float* ET  = Wil + 64 * KP * 4;        // LNUM*ETSTR*2 floats (expT, j-pair packed)
    float* Tsm = ET  + LNUM * ETSTR * 2;   // LNUM*LNUM floats (raw T for edge potential)
    __shared__ float red[4];
    __shared__ int  s_is64;

    const int tid = threadIdx.x;
    const int b0  = blockIdx.x * BPB;

    // ---- prefetch X tile for position 0 ----
    {
        const float* base = X + (size_t)b0 * MLEN * DDIM;  // position 0
        #pragma unroll 4
        for (int v = tid; v < BPB * 32; v += NTHR) {
            int r = v >> 5, c4 = v & 31;
            uint32_t dst = (uint32_t)__cvta_generic_to_shared(&Xs0[r * XSTR + c4 * 4]);
            cp16(dst, base + (size_t)r * MLEN * DDIM + c4 * 4);
        }
        asm volatile("cp.async.commit_group;");
    }

    // ---- stage W interleaved: Wil[dp][kp] = float4(W[2kp][2dp], W[2kp+1][2dp], W[2kp][2dp+1], W[2kp+1][2dp+1]) ----
    for (int i = tid; i < 64 * KP; i += NTHR) {
        int dp = i / KP, kp = i - dp * KP;
        float4 w;
        w.x = W[(2 * kp)     * DDIM + 2 * dp];
        w.y = W[(2 * kp + 1) * DDIM + 2 * dp];
        w.z = W[(2 * kp)     * DDIM + 2 * dp + 1];
        w.w = W[(2 * kp + 1) * DDIM + 2 * dp + 1];
        ((float4*)Wil)[i] = w;
    }
    // ---- stage expT (packed j-pairs, padded rows) and raw T ----
    for (int i = tid; i < LNUM * ETSTR; i += NTHR) {
        int k = i / ETSTR, jp = i - k * ETSTR;
        float2 e = make_float2(0.f, 0.f);
        if (jp < KP) {
            e.x = __expf(T[k * LNUM + 2 * jp]);
            e.y = __expf(T[k * LNUM + 2 * jp + 1]);
        }
        ((float2*)ET)[i] = e;
    }
    for (int i = tid; i < LNUM * LNUM; i += NTHR) Tsm[i] = T[i];

    // ---- detect whether Y is int64 or int32 (labels 0..25; int64 LE has zero high words) ----
    if (tid == 0) {
        const int* y32 = (const int*)Yv;
        int nz = 0;
        for (int i = 1; i < 128; i += 2) nz |= y32[i];
        s_is64 = (nz == 0) ? 1 : 0;
    }
    __syncthreads();

    const bool is64 = (s_is64 != 0);
    const int  b    = b0 + tid;
    const long long* Y64 = (const long long*)Yv;
    const int*       Y32 = (const int*)Yv;

    int ycur = is64 ? (int)Y64[(size_t)b * MLEN] : Y32[(size_t)b * MLEN];

    float a[LNUM];
    #pragma unroll
    for (int k = 0; k < LNUM; k++) a[k] = 1.0f;   // linear alpha, scale csc=0 <=> alpha=0
    float node = 0.f, edge = 0.f, csc = 0.f, logz = 0.f;

    for (int s = 0; s < MLEN; s++) {
        // guard: all threads done reading the buffer we are about to refill
        __syncthreads();
        if (s + 1 < MLEN) {
            float* nbuf = ((s + 1) & 1) ? Xs1 : Xs0;
            const float* base = X + ((size_t)b0 * MLEN + (s + 1)) * DDIM;
            #pragma unroll 4
            for (int v = tid; v < BPB * 32; v += NTHR) {
                int r = v >> 5, c4 = v & 31;
                uint32_t dst = (uint32_t)__cvta_generic_to_shared(&nbuf[r * XSTR + c4 * 4]);
                cp16(dst, base + (size_t)r * MLEN * DDIM + c4 * 4);
            }
            asm volatile("cp.async.commit_group;");
            asm volatile("cp.async.wait_group 1;");
        } else {
            asm volatile("cp.async.wait_group 0;");
        }
        __syncthreads();

        float* buf = (s & 1) ? Xs1 : Xs0;

        // ---- emissions: emit[k] = <W[k], x>, packed over k-pairs (f32x2) ----
        unsigned long long acc[KP];
        #pragma unroll
        for (int kp = 0; kp < KP; kp++) acc[kp] = 0ull;

        const float4*     xr = (const float4*)&buf[tid * XSTR];
        const ulonglong2* Wp = (const ulonglong2*)Wil;
        #pragma unroll 8
        for (int ch = 0; ch < 32; ch++) {
            float4 x = xr[ch];
            unsigned long long x0 = pack2(x.x, x.x), x1 = pack2(x.y, x.y);
            unsigned long long x2 = pack2(x.z, x.z), x3 = pack2(x.w, x.w);
            const ulonglong2* w0 = Wp + (2 * ch) * KP;
            const ulonglong2* w1 = w0 + KP;
            #pragma unroll
            for (int kp = 0; kp < KP; kp++) {
                ulonglong2 wa = w0[kp];
                ffma2(acc[kp], x0, wa.x);
                ffma2(acc[kp], x1, wa.y);
            }
            #pragma unroll
            for (int kp = 0; kp < KP; kp++) {
                ulonglong2 wb = w1[kp];
                ffma2(acc[kp], x2, wb.x);
                ffma2(acc[kp], x3, wb.y);
            }
        }

        float emit[LNUM];
        #pragma unroll
        for (int kp = 0; kp < KP; kp++) unpack2(acc[kp], emit[2 * kp], emit[2 * kp + 1]);

        // node potential: emit[ycur] via static unrolled select (no dynamic reg indexing)
        #pragma unroll
        for (int k = 0; k < LNUM; k++) if (ycur == k) node += emit[k];

        if (s + 1 < MLEN) {
            int ynext = is64 ? (int)Y64[(size_t)b * MLEN + s + 1] : Y32[(size_t)b * MLEN + s + 1];
            edge += Tsm[ycur * LNUM + ynext];

            // linear-domain forward step: s[j] = sum_k (a[k]*exp(emit[k])) * expT[k][j]
            unsigned long long s2[KP];
            #pragma unroll
            for (int kp = 0; kp < KP; kp++) s2[kp] = 0ull;
            const ulonglong2* ETp = (const ulonglong2*)ET;
            #pragma unroll
            for (int k = 0; k < LNUM; k++) {
                float e  = __expf(emit[k]);
                float bk = (s == 0) ? e : a[k] * e;
                unsigned long long bd = pack2(bk, bk);
                const ulonglong2* er = ETp + k * (ETSTR / 2);
                #pragma unroll
                for (int j2 = 0; j2 < 7; j2++) {
                    ulonglong2 e2 = er[j2];
                    ffma2(s2[2 * j2], bd, e2.x);
                    if (2 * j2 + 1 < KP) ffma2(s2[2 * j2 + 1], bd, e2.y);
                }
            }
            float sv[LNUM];
            #pragma unroll
            for (int kp = 0; kp < KP; kp++) unpack2(s2[kp], sv[2 * kp], sv[2 * kp + 1]);
            float m = sv[0];
            #pragma unroll
            for (int k = 1; k < LNUM; k++) m = fmaxf(m, sv[k]);
            float inv = __fdividef(1.0f, m);
            #pragma unroll
            for (int k = 0; k < LNUM; k++) a[k] = sv[k] * inv;
            csc += __logf(m);
            ycur = ynext;
        } else {
            // log partition: csc + log(sum_k a[k]*exp(emit[k]))
            float ssum = 0.f;
            #pragma unroll
            for (int k = 0; k < LNUM; k++) ssum += a[k] * __expf(emit[k]);
            logz = csc + __logf(ssum);
        }
    }

    // contribution to total loss: sum_b (logz - node - edge)
    float val = logz - node - edge;
    #pragma unroll
    for (int o = 16; o; o >>= 1) val += __shfl_xor_sync(0xffffffffu, val, o);
    if ((tid & 31) == 0) red[tid >> 5] = val;
    __syncthreads();
    if (tid == 0) g_partials[blockIdx.x] = red[0] + red[1] + red[2] + red[3];
}

__global__ void crf_reduce(float* __restrict__ out, int n)
{
    int tid = threadIdx.x;
    float v = (tid < n) ? g_partials[tid] : 0.f;
    #pragma unroll
    for (int o = 16; o; o >>= 1) v += __shfl_xor_sync(0xffffffffu, v, o);
    __shared__ float red[16];
    if ((tid & 31) == 0) red[tid >> 5] = v;
    __syncthreads();
    if (tid == 0) {
        float s = 0.f;
        #pragma unroll
        for (int i = 0; i < 16; i++) s += red[i];
        out[0] = s;
    }
}

extern "C" void kernel_launch(void* const* d_in, const int* in_sizes, int n_in,
                              void* d_out, int out_size)
{
    const float* X = (const float*)d_in[0];
    const void*  Y = d_in[1];
    const float* W = (const float*)d_in[2];
    const float* T = (const float*)d_in[3];

    int nb   = in_sizes[0] / (MLEN * DDIM);   // 16384
    int grid = nb / BPB;                      // 128

    size_t smem = (size_t)(2 * BPB * XSTR + 64 * KP * 4 + LNUM * ETSTR * 2 + LNUM * LNUM) * sizeof(float);
    cudaFuncSetAttribute(crf_main, cudaFuncAttributeMaxDynamicSharedMemorySize, (int)smem);

    crf_main<<<grid, NTHR, smem>>>(X, Y, W, T);
    crf_reduce<<<1, 512>>>((float*)d_out, grid);
}

// round 3
// speedup vs baseline: 1.7480x; 1.7480x over previous
#include <cuda_runtime.h>
#include <cstdint>

#define MLEN  16
#define DDIM  128
#define LNUM  26
#define KP    13
#define BPB   128     // words per block
#define NTHR  256     // 8 warps
#define XSTR  132     // padded floats per X row (conflict-free fragment loads)
#define DSTR  36      // padded floats per D row (16B-aligned per row)
#define ETSTR 14
#define NBUF  2

// ---- smem layout (floats) ----
#define XS_F    (BPB * XSTR)                  // 16896 per buffer
#define XOFF(b) ((b) * XS_F)
#define BPOFF   (NBUF * XS_F)                 // Bp: 16kt*4nt*32lane*2 = 4096 floats
#define DOFF    (BPOFF + 4096)                // Dsm: 128*36 = 4608
#define ETOFF   (DOFF + BPB * DSTR)           // expT: 26*14*2 = 728
#define TSOFF   (ETOFF + LNUM * ETSTR * 2)    // T: 676
#define REDOFF  (TSOFF + LNUM * LNUM)         // 4 warp partials
#define FLGOFF  (REDOFF + 4)
#define SMEM_F  (FLGOFF + 4)
#define SMEM_BYTES (SMEM_F * 4)

__device__ float g_partials[512];

// ---------------- helpers ----------------
static __device__ __forceinline__ unsigned long long pack2(float lo, float hi){
    unsigned long long r; asm("mov.b64 %0, {%1,%2};" : "=l"(r) : "f"(lo), "f"(hi)); return r;
}
static __device__ __forceinline__ void unpack2(unsigned long long v, float& lo, float& hi){
    asm("mov.b64 {%0,%1}, %2;" : "=f"(lo), "=f"(hi) : "l"(v));
}
static __device__ __forceinline__ void ffma2(unsigned long long& d, unsigned long long a, unsigned long long b){
    asm("fma.rn.f32x2 %0, %1, %2, %0;" : "+l"(d) : "l"(a), "l"(b));
}
static __device__ __forceinline__ void cp16(uint32_t dst, const void* src){
    asm volatile("cp.async.cg.shared.global [%0], [%1], 16;" :: "r"(dst), "l"(src));
}
static __device__ __forceinline__ uint32_t f2tf(float f){
    uint32_t r; asm("cvt.rna.tf32.f32 %0, %1;" : "=r"(r) : "f"(f)); return r;
}
static __device__ __forceinline__ void mma_tf32(float* d, uint32_t a0, uint32_t a1, uint32_t a2, uint32_t a3,
                                                uint32_t b0, uint32_t b1){
    asm volatile("mma.sync.aligned.m16n8k8.row.col.f32.tf32.tf32.f32 "
                 "{%0,%1,%2,%3}, {%4,%5,%6,%7}, {%8,%9}, {%0,%1,%2,%3};"
                 : "+f"(d[0]), "+f"(d[1]), "+f"(d[2]), "+f"(d[3])
                 : "r"(a0), "r"(a1), "r"(a2), "r"(a3), "r"(b0), "r"(b1));
}

// stage X(position s) for all 128 words of this block into buffer buf
static __device__ __forceinline__ void stage_x(float* sm, const float4* X4, int b0, int s, int buf, int tid){
    uint32_t base = (uint32_t)__cvta_generic_to_shared(sm + XOFF(buf));
    #pragma unroll 4
    for (int v = tid; v < BPB * 32; v += NTHR) {
        int i = v >> 5, f = v & 31;                 // word-row, float4 within row
        uint32_t dst = base + (uint32_t)(i * XSTR + f * 4) * 4u;
        cp16(dst, X4 + ((size_t)(b0 + i) * MLEN + s) * 32 + f);
    }
    asm volatile("cp.async.commit_group;" ::: "memory");
}

__global__ __launch_bounds__(NTHR, 1)
void crf_main(const float* __restrict__ X, const void* __restrict__ Yv,
              const float* __restrict__ W, const float* __restrict__ T)
{
    extern __shared__ float sm[];
    const int tid  = threadIdx.x;
    const int wid  = tid >> 5;
    const int lane = tid & 31;
    const int g    = lane >> 2, t = lane & 3;       // mma groupID / threadID-in-group
    const int b0   = blockIdx.x * BPB;
    const float4* X4 = (const float4*)X;

    // prefetch first two positions immediately
    stage_x(sm, X4, b0, 0, 0, tid);
    stage_x(sm, X4, b0, 1, 1, tid);

    // ---- build pre-permuted tf32 B fragments: Bp[(kt*4+nt)*32+lane] = {W[n][k0], W[n][k1]} ----
    float* Bp = sm + BPOFF;
    for (int i = tid; i < 16 * 4 * 32; i += NTHR) {
        int kt = i >> 7, rem = i & 127, nt = rem >> 5, ln = rem & 31;
        int n  = nt * 8 + (ln >> 2);
        int k0 = kt * 8 + (ln & 3);
        float w0 = (n < LNUM) ? W[n * DDIM + k0]     : 0.f;
        float w1 = (n < LNUM) ? W[n * DDIM + k0 + 4] : 0.f;
        Bp[2 * i]     = __uint_as_float(f2tf(w0));
        Bp[2 * i + 1] = __uint_as_float(f2tf(w1));
    }
    // ---- expT (packed j-pairs), raw T, Y dtype flag ----
    float* ET  = sm + ETOFF;
    float* Tsm = sm + TSOFF;
    for (int i = tid; i < LNUM * ETSTR; i += NTHR) {
        int k = i / ETSTR, jp = i - k * ETSTR;
        float2 e = make_float2(0.f, 0.f);
        if (jp < KP) { e.x = __expf(T[k * LNUM + 2 * jp]); e.y = __expf(T[k * LNUM + 2 * jp + 1]); }
        ((float2*)ET)[i] = e;
    }
    for (int i = tid; i < LNUM * LNUM; i += NTHR) Tsm[i] = T[i];
    if (tid == 0) {
        const int* y32 = (const int*)Yv;
        int nz = 0;
        for (int i = 1; i < 128; i += 2) nz |= y32[i];
        ((int*)sm)[FLGOFF] = (nz == 0) ? 1 : 0;
    }
    __syncthreads();

    const bool is64 = ((int*)sm)[FLGOFF] != 0;
    const long long* Y64 = (const long long*)Yv;
    const int*       Y32 = (const int*)Yv;
    const int b = b0 + tid;   // only meaningful for tid < 128

    int ycur = 0;
    if (tid < BPB) ycur = is64 ? (int)Y64[(size_t)b * MLEN] : Y32[(size_t)b * MLEN];

    float a[LNUM];
    #pragma unroll
    for (int k = 0; k < LNUM; k++) a[k] = 1.0f;
    float node = 0.f, edge = 0.f, csc = 0.f, logz = 0.f;

    float* Dsm = sm + DOFF;

    for (int s = 0; s < MLEN; s++) {
        const int buf = s & 1;

        if (s <= 14) asm volatile("cp.async.wait_group 1;" ::: "memory");
        else         asm volatile("cp.async.wait_group 0;" ::: "memory");
        __syncthreads();

        // ---- GEMM: warp wid computes rows [wid*16, wid*16+16) x N=32, K=128 ----
        {
            float acc[4][4];
            #pragma unroll
            for (int nt = 0; nt < 4; nt++)
                #pragma unroll
                for (int r = 0; r < 4; r++) acc[nt][r] = 0.f;

            const float* Xb = sm + XOFF(buf) + (wid * 16) * XSTR;
            #pragma unroll
            for (int kt = 0; kt < 16; kt++) {
                // B fragments (lane-contiguous, conflict-free)
                const float2* bp = (const float2*)(Bp + (kt * 4) * 64);
                float2 bf0 = bp[0 * 32 + lane];
                float2 bf1 = bp[1 * 32 + lane];
                float2 bf2 = bp[2 * 32 + lane];
                float2 bf3 = bp[3 * 32 + lane];
                // A fragments
                const float* xp = Xb + g * XSTR + kt * 8 + t;
                uint32_t a0 = f2tf(xp[0]);
                uint32_t a2 = f2tf(xp[4]);
                uint32_t a1 = f2tf(xp[8 * XSTR]);
                uint32_t a3 = f2tf(xp[8 * XSTR + 4]);
                mma_tf32(acc[0], a0, a1, a2, a3, __float_as_uint(bf0.x), __float_as_uint(bf0.y));
                mma_tf32(acc[1], a0, a1, a2, a3, __float_as_uint(bf1.x), __float_as_uint(bf1.y));
                mma_tf32(acc[2], a0, a1, a2, a3, __float_as_uint(bf2.x), __float_as_uint(bf2.y));
                mma_tf32(acc[3], a0, a1, a2, a3, __float_as_uint(bf3.x), __float_as_uint(bf3.y));
            }
            // write D tile to smem
            int r0 = wid * 16 + g;
            #pragma unroll
            for (int nt = 0; nt < 4; nt++) {
                int c = nt * 8 + t * 2;
                *(float2*)&Dsm[r0 * DSTR + c]       = make_float2(acc[nt][0], acc[nt][1]);
                *(float2*)&Dsm[(r0 + 8) * DSTR + c] = make_float2(acc[nt][2], acc[nt][3]);
            }
        }
        __syncthreads();

        // refill this buffer with X(s+2) — all GEMM reads of it are done
        if (s + 2 < MLEN) stage_x(sm, X4, b0, s + 2, buf, tid);

        // ---- recurrence: threads 0..127, one word each ----
        if (tid < BPB) {
            float ef[LNUM];
            const float4* dr = (const float4*)&Dsm[tid * DSTR];
            #pragma unroll
            for (int q = 0; q < 6; q++) {
                float4 v = dr[q];
                ef[4 * q] = v.x; ef[4 * q + 1] = v.y; ef[4 * q + 2] = v.z; ef[4 * q + 3] = v.w;
            }
            { float2 v = *(const float2*)&Dsm[tid * DSTR + 24]; ef[24] = v.x; ef[25] = v.y; }

            #pragma unroll
            for (int k = 0; k < LNUM; k++) if (ycur == k) node += ef[k];

            if (s + 1 < MLEN) {
                int ynext = is64 ? (int)Y64[(size_t)b * MLEN + s + 1] : Y32[(size_t)b * MLEN + s + 1];
                edge += Tsm[ycur * LNUM + ynext];

                unsigned long long s2[KP];
                #pragma unroll
                for (int kp = 0; kp < KP; kp++) s2[kp] = 0ull;
                const ulonglong2* ETp = (const ulonglong2*)ET;
                #pragma unroll
                for (int k = 0; k < LNUM; k++) {
                    float e  = __expf(ef[k]);
                    float bk = (s == 0) ? e : a[k] * e;
                    unsigned long long bd = pack2(bk, bk);
                    const ulonglong2* er = ETp + k * (ETSTR / 2);
                    #pragma unroll
                    for (int j2 = 0; j2 < 7; j2++) {
                        ulonglong2 e2 = er[j2];
                        ffma2(s2[2 * j2], bd, e2.x);
                        if (2 * j2 + 1 < KP) ffma2(s2[2 * j2 + 1], bd, e2.y);
                    }
                }
                float sv[LNUM];
                #pragma unroll
                for (int kp = 0; kp < KP; kp++) unpack2(s2[kp], sv[2 * kp], sv[2 * kp + 1]);
                float m = sv[0];
                #pragma unroll
                for (int k = 1; k < LNUM; k++) m = fmaxf(m, sv[k]);
                float inv = __fdividef(1.0f, m);
                #pragma unroll
                for (int k = 0; k < LNUM; k++) a[k] = sv[k] * inv;
                csc += __logf(m);
                ycur = ynext;
            } else {
                float ssum = 0.f;
                #pragma unroll
                for (int k = 0; k < LNUM; k++) ssum += a[k] * __expf(ef[k]);
                logz = csc + __logf(ssum);
            }
        }
    }

    // ---- block reduction over threads 0..127 ----
    float val = (tid < BPB) ? (logz - node - edge) : 0.f;
    #pragma unroll
    for (int o = 16; o; o >>= 1) val += __shfl_xor_sync(0xffffffffu, val, o);
    float* red = sm + REDOFF;
    if (wid < 4 && lane == 0) red[wid] = val;
    __syncthreads();
    if (tid == 0) g_partials[blockIdx.x] = red[0] + red[1] + red[2] + red[3];
}

__global__ void crf_reduce(float* __restrict__ out, int n)
{
    int tid = threadIdx.x;
    float v = (tid < n) ? g_partials[tid] : 0.f;
    #pragma unroll
    for (int o = 16; o; o >>= 1) v += __shfl_xor_sync(0xffffffffu, v, o);
    __shared__ float red[16];
    if ((tid & 31) == 0) red[tid >> 5] = v;
    __syncthreads();
    if (tid == 0) {
        float s = 0.f;
        #pragma unroll
        for (int i = 0; i < 16; i++) s += red[i];
        out[0] = s;
    }
}

extern "C" void kernel_launch(void* const* d_in, const int* in_sizes, int n_in,
                              void* d_out, int out_size)
{
    const float* X = (const float*)d_in[0];
    const void*  Y = d_in[1];
    const float* W = (const float*)d_in[2];
    const float* T = (const float*)d_in[3];

    int nb   = in_sizes[0] / (MLEN * DDIM);   // 16384
    int grid = nb / BPB;                      // 128

    cudaFuncSetAttribute(crf_main, cudaFuncAttributeMaxDynamicSharedMemorySize, SMEM_BYTES);
    crf_main<<<grid, NTHR, SMEM_BYTES>>>(X, Y, W, T);
    crf_reduce<<<1, 512>>>((float*)d_out, grid);
}

// round 4
// speedup vs baseline: 1.8713x; 1.0705x over previous
#include <cuda_runtime.h>
#include <cstdint>

#define MLEN  16
#define DDIM  128
#define LNUM  26
#define KP    13
#define BPB   64      // words per block
#define NTHR  128     // 4 warps
#define GRID  256
#define XSTR  136     // padded floats per X row (conflict-free float2 fragment loads)
#define DSTR  36
#define ETSTR 14
#define NBUF  2

// ---- smem layout (float indices) ----
#define XS_F    (BPB * XSTR)                  // 8704 per buffer
#define XOFF(b) ((b) * XS_F)
#define BPOFF   (NBUF * XS_F)                 // 17408: Bp 8kt*4nt*32lane uint2 = 2048 floats
#define DOFF    (BPOFF + 2048)                // 19456: D 64*36 = 2304
#define ETOFF   (DOFF + BPB * DSTR)           // 21760: expT 728
#define TSOFF   (ETOFF + LNUM * ETSTR * 2)    // 22488: T 676
#define REDOFF  (TSOFF + LNUM * LNUM)         // 23164
#define FLGOFF  (REDOFF + 4)                  // 23168
#define SMEM_F  (FLGOFF + 4)
#define SMEM_BYTES (SMEM_F * 4)               // ~92.7 KB -> 2 blocks/SM

__device__ float g_partials[GRID];
__device__ unsigned int g_count;

// ---------------- helpers ----------------
static __device__ __forceinline__ unsigned long long pack2(float lo, float hi){
    unsigned long long r; asm("mov.b64 %0, {%1,%2};" : "=l"(r) : "f"(lo), "f"(hi)); return r;
}
static __device__ __forceinline__ void unpack2(unsigned long long v, float& lo, float& hi){
    asm("mov.b64 {%0,%1}, %2;" : "=f"(lo), "=f"(hi) : "l"(v));
}
static __device__ __forceinline__ void ffma2(unsigned long long& d, unsigned long long a, unsigned long long b){
    asm("fma.rn.f32x2 %0, %1, %2, %0;" : "+l"(d) : "l"(a), "l"(b));
}
static __device__ __forceinline__ void cp16(uint32_t dst, const void* src){
    asm volatile("cp.async.cg.shared.global [%0], [%1], 16;" :: "r"(dst), "l"(src));
}
// pack two f32 into bf16x2: {lo, hi}
static __device__ __forceinline__ uint32_t bfpack(float lo, float hi){
    uint32_t r; asm("cvt.rn.bf16x2.f32 %0, %1, %2;" : "=r"(r) : "f"(hi), "f"(lo)); return r;
}
static __device__ __forceinline__ void mma_bf16(float* d, uint32_t a0, uint32_t a1, uint32_t a2, uint32_t a3,
                                                uint32_t b0, uint32_t b1){
    asm volatile("mma.sync.aligned.m16n8k16.row.col.f32.bf16.bf16.f32 "
                 "{%0,%1,%2,%3}, {%4,%5,%6,%7}, {%8,%9}, {%0,%1,%2,%3};"
                 : "+f"(d[0]), "+f"(d[1]), "+f"(d[2]), "+f"(d[3])
                 : "r"(a0), "r"(a1), "r"(a2), "r"(a3), "r"(b0), "r"(b1));
}

// stage X(position s) for the block's 64 words into buffer buf
static __device__ __forceinline__ void stage_x(float* sm, const float4* X4, int b0, int s, int buf, int tid){
    uint32_t base = (uint32_t)__cvta_generic_to_shared(sm + XOFF(buf));
    #pragma unroll 4
    for (int v = tid; v < BPB * 32; v += NTHR) {
        int i = v >> 5, f = v & 31;
        uint32_t dst = base + (uint32_t)(i * XSTR + f * 4) * 4u;
        cp16(dst, X4 + ((size_t)(b0 + i) * MLEN + s) * 32 + f);
    }
    asm volatile("cp.async.commit_group;" ::: "memory");
}

__global__ __launch_bounds__(NTHR, 2)
void crf_main(const float* __restrict__ X, const void* __restrict__ Yv,
              const float* __restrict__ W, const float* __restrict__ T,
              float* __restrict__ out)
{
    extern __shared__ float sm[];
    const int tid  = threadIdx.x;
    const int wid  = tid >> 5;
    const int lane = tid & 31;
    const int g    = lane >> 2, t = lane & 3;
    const int b0   = blockIdx.x * BPB;
    const float4* X4 = (const float4*)X;

    stage_x(sm, X4, b0, 0, 0, tid);
    stage_x(sm, X4, b0, 1, 1, tid);

    // ---- prepack bf16 B fragments: Bp[(kt*4+nt)*32+lane] = uint2{ {W[n][k0],W[n][k0+1]}, {W[n][k0+8],W[n][k0+9]} } ----
    uint2* Bp = (uint2*)(sm + BPOFF);
    for (int i = tid; i < 8 * 4 * 32; i += NTHR) {
        int kt = i >> 7, rem = i & 127, nt = rem >> 5, ln = rem & 31;
        int n  = nt * 8 + (ln >> 2);
        int k0 = kt * 16 + (ln & 3) * 2;
        float w0 = 0.f, w1 = 0.f, w2 = 0.f, w3 = 0.f;
        if (n < LNUM) {
            w0 = W[n * DDIM + k0];     w1 = W[n * DDIM + k0 + 1];
            w2 = W[n * DDIM + k0 + 8]; w3 = W[n * DDIM + k0 + 9];
        }
        Bp[i] = make_uint2(bfpack(w0, w1), bfpack(w2, w3));
    }
    float* ET  = sm + ETOFF;
    float* Tsm = sm + TSOFF;
    for (int i = tid; i < LNUM * ETSTR; i += NTHR) {
        int k = i / ETSTR, jp = i - k * ETSTR;
        float2 e = make_float2(0.f, 0.f);
        if (jp < KP) { e.x = __expf(T[k * LNUM + 2 * jp]); e.y = __expf(T[k * LNUM + 2 * jp + 1]); }
        ((float2*)ET)[i] = e;
    }
    for (int i = tid; i < LNUM * LNUM; i += NTHR) Tsm[i] = T[i];
    if (tid == 0) {
        const int* y32 = (const int*)Yv;
        int nz = 0;
        for (int i = 1; i < 128; i += 2) nz |= y32[i];
        ((int*)sm)[FLGOFF] = (nz == 0) ? 1 : 0;
    }
    __syncthreads();

    const bool is64 = ((int*)sm)[FLGOFF] != 0;
    const long long* Y64 = (const long long*)Yv;
    const int*       Y32 = (const int*)Yv;
    const int b = b0 + tid;   // word index for tid < 64

    int ycur = 0;
    if (tid < BPB) ycur = is64 ? (int)Y64[(size_t)b * MLEN] : Y32[(size_t)b * MLEN];

    float a[LNUM];
    #pragma unroll
    for (int k = 0; k < LNUM; k++) a[k] = 1.0f;
    float node = 0.f, edge = 0.f, csc = 0.f, logz = 0.f;

    float* Dsm = sm + DOFF;

    for (int s = 0; s < MLEN; s++) {
        const int buf = s & 1;

        if (s < MLEN - 1) asm volatile("cp.async.wait_group 1;" ::: "memory");
        else              asm volatile("cp.async.wait_group 0;" ::: "memory");
        __syncthreads();   // X(s) visible to all; D(s-1) fully consumed

        // ---- GEMM: warp wid computes rows [wid*16, wid*16+16) x N=32, K=128, bf16 ----
        {
            float acc[4][4];
            #pragma unroll
            for (int nt = 0; nt < 4; nt++)
                #pragma unroll
                for (int r = 0; r < 4; r++) acc[nt][r] = 0.f;

            const float* Xb = sm + XOFF(buf) + (wid * 16) * XSTR;
            #pragma unroll
            for (int kt = 0; kt < 8; kt++) {
                const float* xp = Xb + g * XSTR + kt * 16 + t * 2;
                float2 v0 = *(const float2*)(xp);
                float2 v2 = *(const float2*)(xp + 8);
                float2 v1 = *(const float2*)(xp + 8 * XSTR);
                float2 v3 = *(const float2*)(xp + 8 * XSTR + 8);
                uint32_t a0 = bfpack(v0.x, v0.y);
                uint32_t a1 = bfpack(v1.x, v1.y);
                uint32_t a2 = bfpack(v2.x, v2.y);
                uint32_t a3 = bfpack(v3.x, v3.y);
                const uint2* bp = Bp + (kt * 4) * 32 + lane;
                uint2 bf0 = bp[0];
                uint2 bf1 = bp[32];
                uint2 bf2 = bp[64];
                uint2 bf3 = bp[96];
                mma_bf16(acc[0], a0, a1, a2, a3, bf0.x, bf0.y);
                mma_bf16(acc[1], a0, a1, a2, a3, bf1.x, bf1.y);
                mma_bf16(acc[2], a0, a1, a2, a3, bf2.x, bf2.y);
                mma_bf16(acc[3], a0, a1, a2, a3, bf3.x, bf3.y);
            }
            int r0 = wid * 16 + g;
            #pragma unroll
            for (int nt = 0; nt < 4; nt++) {
                int c = nt * 8 + t * 2;
                *(float2*)&Dsm[r0 * DSTR + c]       = make_float2(acc[nt][0], acc[nt][1]);
                *(float2*)&Dsm[(r0 + 8) * DSTR + c] = make_float2(acc[nt][2], acc[nt][3]);
            }
        }
        __syncthreads();   // D(s) visible; X(buf) fully consumed

        if (s + 2 < MLEN) stage_x(sm, X4, b0, s + 2, buf, tid);

        // ---- recurrence: threads 0..63, one word each ----
        if (tid < BPB) {
            float ef[LNUM];
            const float4* dr = (const float4*)&Dsm[tid * DSTR];
            #pragma unroll
            for (int q = 0; q < 6; q++) {
                float4 v = dr[q];
                ef[4 * q] = v.x; ef[4 * q + 1] = v.y; ef[4 * q + 2] = v.z; ef[4 * q + 3] = v.w;
            }
            { float2 v = *(const float2*)&Dsm[tid * DSTR + 24]; ef[24] = v.x; ef[25] = v.y; }

            #pragma unroll
            for (int k = 0; k < LNUM; k++) if (ycur == k) node += ef[k];

            if (s + 1 < MLEN) {
                int ynext = is64 ? (int)Y64[(size_t)b * MLEN + s + 1] : Y32[(size_t)b * MLEN + s + 1];
                edge += Tsm[ycur * LNUM + ynext];

                unsigned long long s2[KP];
                #pragma unroll
                for (int kp = 0; kp < KP; kp++) s2[kp] = 0ull;
                const ulonglong2* ETp = (const ulonglong2*)ET;
                #pragma unroll
                for (int k = 0; k < LNUM; k++) {
                    float e  = __expf(ef[k]);
                    float bk = (s == 0) ? e : a[k] * e;
                    unsigned long long bd = pack2(bk, bk);
                    const ulonglong2* er = ETp + k * (ETSTR / 2);
                    #pragma unroll
                    for (int j2 = 0; j2 < 7; j2++) {
                        ulonglong2 e2 = er[j2];
                        ffma2(s2[2 * j2], bd, e2.x);
                        if (2 * j2 + 1 < KP) ffma2(s2[2 * j2 + 1], bd, e2.y);
                    }
                }
                float sv[LNUM];
                #pragma unroll
                for (int kp = 0; kp < KP; kp++) unpack2(s2[kp], sv[2 * kp], sv[2 * kp + 1]);
                float m = sv[0];
                #pragma unroll
                for (int k = 1; k < LNUM; k++) m = fmaxf(m, sv[k]);
                float inv = __fdividef(1.0f, m);
                #pragma unroll
                for (int k = 0; k < LNUM; k++) a[k] = sv[k] * inv;
                csc += __logf(m);
                ycur = ynext;
            } else {
                float ssum = 0.f;
                #pragma unroll
                for (int k = 0; k < LNUM; k++) ssum += a[k] * __expf(ef[k]);
                logz = csc + __logf(ssum);
            }
        }
    }

    // ---- block reduction (threads 0..63 hold values) ----
    float val = (tid < BPB) ? (logz - node - edge) : 0.f;
    #pragma unroll
    for (int o = 16; o; o >>= 1) val += __shfl_xor_sync(0xffffffffu, val, o);
    float* red = sm + REDOFF;
    if (lane == 0) red[wid] = val;
    __syncthreads();

    // ---- deterministic last-block global reduction ----
    __shared__ int s_last;
    if (tid == 0) {
        g_partials[blockIdx.x] = red[0] + red[1];   // warps 2,3 contribute 0
        __threadfence();
        unsigned int old = atomicAdd(&g_count, 1u);
        s_last = (old == (unsigned)(gridDim.x - 1)) ? 1 : 0;
    }
    __syncthreads();
    if (s_last && tid < 32) {
        __threadfence();
        const volatile float* gp = (const volatile float*)g_partials;
        float v = 0.f;
        #pragma unroll
        for (int i = 0; i < GRID / 32; i++) v += gp[lane + i * 32];  // fixed order
        #pragma unroll
        for (int o = 16; o; o >>= 1) v += __shfl_xor_sync(0xffffffffu, v, o);
        if (lane == 0) { out[0] = v; g_count = 0; }
    }
}

extern "C" void kernel_launch(void* const* d_in, const int* in_sizes, int n_in,
                              void* d_out, int out_size)
{
    const float* X = (const float*)d_in[0];
    const void*  Y = d_in[1];
    const float* W = (const float*)d_in[2];
    const float* T = (const float*)d_in[3];

    cudaFuncSetAttribute(crf_main, cudaFuncAttributeMaxDynamicSharedMemorySize, SMEM_BYTES);
    crf_main<<<GRID, NTHR, SMEM_BYTES>>>(X, Y, W, T, (float*)d_out);
}